// round 13
// baseline (speedup 1.0000x reference)
#include <cuda_runtime.h>
#include <cuda_bf16.h>
#include <math.h>
#include <stdint.h>

// x: (16, 256, 64, 64, 4) f32. Per (b,c) slab = 4096 float4 = 64 KB.
// L2-chunked pipeline, serial launch chain, role-separated blocks:
//   chunks: [0], [1,2], [3,4], ..., [13,14], [15]   (tapered ends)
//   L0:  pool(c0)
//   Lk:  combined scale(c_{k-1}) + pool(c_k)
//   L9:  scale(c8)
// Pool unit = full slab (64 KB DRAM read). Scale unit = half slab
// (32 KB L2 read + 32 KB PLAIN write). Bresenham role interleave keeps the
// per-SM read/write mix even for unequal unit counts.
// Stores are plain write-back: stcs measured ~5.0 TB/s vs plain 6.2 TB/s.

#define NB 16
#define NC 256
#define SP 4096                      // float4 per (b,c)
#define HSP (SP / 2)
#define TPB 256

__device__ float4 g_pooled[NB * NC];

// ---------------------------------------------------------------------------
// Pool one full slab.
// ---------------------------------------------------------------------------
__device__ __forceinline__ void do_pool(const float* __restrict__ x, int bc) {
    const float4* xp = reinterpret_cast<const float4*>(x) + (size_t)bc * SP;
    const int t = threadIdx.x;

    float4 m = make_float4(-INFINITY, -INFINITY, -INFINITY, -INFINITY);
    #pragma unroll
    for (int j0 = 0; j0 < SP / TPB; j0 += 8) {
        float4 v[8];
        #pragma unroll
        for (int j = 0; j < 8; j++) v[j] = xp[t + (j0 + j) * TPB];
        #pragma unroll
        for (int j = 0; j < 8; j++) {
            m.x = fmaxf(m.x, v[j].x);
            m.y = fmaxf(m.y, v[j].y);
            m.z = fmaxf(m.z, v[j].z);
            m.w = fmaxf(m.w, v[j].w);
        }
    }
    #pragma unroll
    for (int o = 16; o > 0; o >>= 1) {
        m.x = fmaxf(m.x, __shfl_xor_sync(0xffffffffu, m.x, o));
        m.y = fmaxf(m.y, __shfl_xor_sync(0xffffffffu, m.y, o));
        m.z = fmaxf(m.z, __shfl_xor_sync(0xffffffffu, m.z, o));
        m.w = fmaxf(m.w, __shfl_xor_sync(0xffffffffu, m.w, o));
    }
    __shared__ float4 red[TPB / 32];
    if ((t & 31) == 0) red[t >> 5] = m;
    __syncthreads();
    if (t == 0) {
        float4 r = red[0];
        #pragma unroll
        for (int w = 1; w < TPB / 32; w++) {
            r.x = fmaxf(r.x, red[w].x);
            r.y = fmaxf(r.y, red[w].y);
            r.z = fmaxf(r.z, red[w].z);
            r.w = fmaxf(r.w, red[w].w);
        }
        g_pooled[bc] = r;
    }
}

// ---------------------------------------------------------------------------
// Scale one half slab: redundant squeeze+excite, then out = x * u.
// ---------------------------------------------------------------------------
__device__ __forceinline__ void do_scale_half(const float* __restrict__ x,
                                              const float* __restrict__ comp_w,
                                              const float* __restrict__ comp_b,
                                              const float* __restrict__ exc_w,
                                              const float* __restrict__ exc_b,
                                              float* __restrict__ out,
                                              int bc, int half) {
    const int b = bc >> 8;
    const int c = bc & 255;
    const int t = threadIdx.x;
    const int lane = t & 31;
    const int warp = t >> 5;

    __shared__ float4 red[TPB / 32];
    __shared__ float4 u_sh;

    float4 p = g_pooled[b * NC + t];
    float s0 = p.x * comp_w[0 * NC + t];
    float s1 = p.y * comp_w[1 * NC + t];
    float s2 = p.z * comp_w[2 * NC + t];
    float s3 = p.w * comp_w[3 * NC + t];
    #pragma unroll
    for (int o = 16; o > 0; o >>= 1) {
        s0 += __shfl_xor_sync(0xffffffffu, s0, o);
        s1 += __shfl_xor_sync(0xffffffffu, s1, o);
        s2 += __shfl_xor_sync(0xffffffffu, s2, o);
        s3 += __shfl_xor_sync(0xffffffffu, s3, o);
    }
    if (lane == 0) red[warp] = make_float4(s0, s1, s2, s3);
    __syncthreads();
    if (t == 0) {
        float r  = comp_b[0];
        float xc = comp_b[1];
        float yc = comp_b[2];
        float zc = comp_b[3];
        #pragma unroll
        for (int w = 0; w < TPB / 32; w++) {
            r  += red[w].x;
            xc += red[w].y;
            yc += red[w].z;
            zc += red[w].w;
        }
        float u1r = r + xc + yc + zc;
        float u1x = xc - r - zc + yc;
        float u1y = yc + zc - r - xc;
        float u1z = zc - yc + xc - r;
        float r2 = u1r * exc_w[0 * NC + c] + exc_b[0 * NC + c];
        float x2 = u1x * exc_w[1 * NC + c] + exc_b[1 * NC + c];
        float y2 = u1y * exc_w[2 * NC + c] + exc_b[2 * NC + c];
        float z2 = u1z * exc_w[3 * NC + c] + exc_b[3 * NC + c];
        u_sh = make_float4(r2 + x2 + y2 + z2,
                           x2 - r2 - z2 + y2,
                           y2 + z2 - r2 - x2,
                           z2 - y2 + x2 - r2);
    }
    __syncthreads();
    const float4 u = u_sh;

    const size_t base = (size_t)bc * SP + (size_t)half * HSP;
    const float4* xp = reinterpret_cast<const float4*>(x) + base;
    float4* op = reinterpret_cast<float4*>(out) + base;
    float4 v[8];
    #pragma unroll
    for (int j = 0; j < 8; j++) v[j] = __ldcs(&xp[t + j * TPB]);
    #pragma unroll
    for (int j = 0; j < 8; j++) {
        op[t + j * TPB] = make_float4(v[j].x * u.x, v[j].y * u.y,
                                      v[j].z * u.z, v[j].w * u.w);
    }
}

// ---------------------------------------------------------------------------
// Generic launch: np pool units (full slabs from pool_b0) and ns scale units
// (half slabs from scale_b0), Bresenham-interleaved over np+ns blocks.
// ---------------------------------------------------------------------------
__global__ void __launch_bounds__(TPB) step_kernel(const float* __restrict__ x,
                                                   const float* __restrict__ comp_w,
                                                   const float* __restrict__ comp_b,
                                                   const float* __restrict__ exc_w,
                                                   const float* __restrict__ exc_b,
                                                   float* __restrict__ out,
                                                   int scale_b0, int ns,
                                                   int pool_b0, int np) {
    const long r = blockIdx.x;
    const long tot = np + ns;
    const int p_lo = (int)((r * np) / tot);
    const int p_hi = (int)(((r + 1) * np) / tot);
    if (p_hi > p_lo) {
        // pool unit index p_lo
        do_pool(x, pool_b0 * NC + p_lo);
    } else {
        const int sidx = (int)r - p_hi;   // scale unit index
        do_scale_half(x, comp_w, comp_b, exc_w, exc_b, out,
                      scale_b0 * NC + (sidx >> 1), sidx & 1);
    }
}

extern "C" void kernel_launch(void* const* d_in, const int* in_sizes, int n_in,
                              void* d_out, int out_size) {
    const float* x      = (const float*)d_in[0];
    const float* comp_w = (const float*)d_in[1];
    const float* comp_b = (const float*)d_in[2];
    const float* exc_w  = (const float*)d_in[3];
    const float* exc_b  = (const float*)d_in[4];
    float* out = (float*)d_out;

    // Chunk table: batch start and count. Tapered: 1,2,2,2,2,2,2,2,1.
    const int cb[9] = {0, 1, 3, 5, 7, 9, 11, 13, 15};
    const int cn[9] = {1, 2, 2, 2, 2, 2, 2, 2, 1};

    // L0: pool chunk 0
    {
        int np = cn[0] * NC;
        step_kernel<<<np, TPB>>>(x, comp_w, comp_b, exc_w, exc_b, out,
                                 0, 0, cb[0], np);
    }
    // L1..L8: combined scale(c_{k-1}) + pool(c_k)
    for (int k = 1; k <= 8; k++) {
        int ns = cn[k - 1] * NC * 2;   // half-slab units
        int np = cn[k] * NC;           // full-slab units
        step_kernel<<<np + ns, TPB>>>(x, comp_w, comp_b, exc_w, exc_b, out,
                                      cb[k - 1], ns, cb[k], np);
    }
    // L9: scale chunk 8
    {
        int ns = cn[8] * NC * 2;
        step_kernel<<<ns, TPB>>>(x, comp_w, comp_b, exc_w, exc_b, out,
                                 cb[8], ns, 0, 0);
    }
}

// round 14
// speedup vs baseline: 1.0880x; 1.0880x over previous
#include <cuda_runtime.h>
#include <cuda_bf16.h>
#include <math.h>
#include <stdint.h>

// x: (16, 256, 64, 64, 4) f32. Per (b,c) slab = 4096 float4 = 64 KB.
// L2-chunked pipeline, serial launch chain, role-separated blocks (R11 config)
// with TAPERED end chunks:
//   chunks: [0], [1,2], [3,4], ..., [13,14], [15]
//   L0: pool(c0); Lk: combined scale(c_{k-1})+pool(c_k); L9: scale(c8)
// Pool unit = full slab (64 KB DRAM read, default loads -> populate L2).
// Scale unit = half slab (32 KB __ldcs L2 read + 32 KB __stcs streamed write).
// __stcs is load-bearing: plain stores write-allocate and evict the pooled
// chunk from L2 (R13 regression).

#define NB 16
#define NC 256
#define SP 4096                      // float4 per (b,c)
#define HSP (SP / 2)
#define TPB 256

__device__ float4 g_pooled[NB * NC];

// ---------------------------------------------------------------------------
// Pool one full slab.
// ---------------------------------------------------------------------------
__device__ __forceinline__ void do_pool(const float* __restrict__ x, int bc) {
    const float4* xp = reinterpret_cast<const float4*>(x) + (size_t)bc * SP;
    const int t = threadIdx.x;

    float4 m = make_float4(-INFINITY, -INFINITY, -INFINITY, -INFINITY);
    #pragma unroll
    for (int j0 = 0; j0 < SP / TPB; j0 += 8) {
        float4 v[8];
        #pragma unroll
        for (int j = 0; j < 8; j++) v[j] = xp[t + (j0 + j) * TPB];
        #pragma unroll
        for (int j = 0; j < 8; j++) {
            m.x = fmaxf(m.x, v[j].x);
            m.y = fmaxf(m.y, v[j].y);
            m.z = fmaxf(m.z, v[j].z);
            m.w = fmaxf(m.w, v[j].w);
        }
    }
    #pragma unroll
    for (int o = 16; o > 0; o >>= 1) {
        m.x = fmaxf(m.x, __shfl_xor_sync(0xffffffffu, m.x, o));
        m.y = fmaxf(m.y, __shfl_xor_sync(0xffffffffu, m.y, o));
        m.z = fmaxf(m.z, __shfl_xor_sync(0xffffffffu, m.z, o));
        m.w = fmaxf(m.w, __shfl_xor_sync(0xffffffffu, m.w, o));
    }
    __shared__ float4 red[TPB / 32];
    if ((t & 31) == 0) red[t >> 5] = m;
    __syncthreads();
    if (t == 0) {
        float4 r = red[0];
        #pragma unroll
        for (int w = 1; w < TPB / 32; w++) {
            r.x = fmaxf(r.x, red[w].x);
            r.y = fmaxf(r.y, red[w].y);
            r.z = fmaxf(r.z, red[w].z);
            r.w = fmaxf(r.w, red[w].w);
        }
        g_pooled[bc] = r;
    }
}

// ---------------------------------------------------------------------------
// Scale one half slab: redundant squeeze+excite, then out = x * u.
// ---------------------------------------------------------------------------
__device__ __forceinline__ void do_scale_half(const float* __restrict__ x,
                                              const float* __restrict__ comp_w,
                                              const float* __restrict__ comp_b,
                                              const float* __restrict__ exc_w,
                                              const float* __restrict__ exc_b,
                                              float* __restrict__ out,
                                              int bc, int half) {
    const int b = bc >> 8;
    const int c = bc & 255;
    const int t = threadIdx.x;
    const int lane = t & 31;
    const int warp = t >> 5;

    __shared__ float4 red[TPB / 32];
    __shared__ float4 u_sh;

    float4 p = g_pooled[b * NC + t];
    float s0 = p.x * comp_w[0 * NC + t];
    float s1 = p.y * comp_w[1 * NC + t];
    float s2 = p.z * comp_w[2 * NC + t];
    float s3 = p.w * comp_w[3 * NC + t];
    #pragma unroll
    for (int o = 16; o > 0; o >>= 1) {
        s0 += __shfl_xor_sync(0xffffffffu, s0, o);
        s1 += __shfl_xor_sync(0xffffffffu, s1, o);
        s2 += __shfl_xor_sync(0xffffffffu, s2, o);
        s3 += __shfl_xor_sync(0xffffffffu, s3, o);
    }
    if (lane == 0) red[warp] = make_float4(s0, s1, s2, s3);
    __syncthreads();
    if (t == 0) {
        float r  = comp_b[0];
        float xc = comp_b[1];
        float yc = comp_b[2];
        float zc = comp_b[3];
        #pragma unroll
        for (int w = 0; w < TPB / 32; w++) {
            r  += red[w].x;
            xc += red[w].y;
            yc += red[w].z;
            zc += red[w].w;
        }
        float u1r = r + xc + yc + zc;
        float u1x = xc - r - zc + yc;
        float u1y = yc + zc - r - xc;
        float u1z = zc - yc + xc - r;
        float r2 = u1r * exc_w[0 * NC + c] + exc_b[0 * NC + c];
        float x2 = u1x * exc_w[1 * NC + c] + exc_b[1 * NC + c];
        float y2 = u1y * exc_w[2 * NC + c] + exc_b[2 * NC + c];
        float z2 = u1z * exc_w[3 * NC + c] + exc_b[3 * NC + c];
        u_sh = make_float4(r2 + x2 + y2 + z2,
                           x2 - r2 - z2 + y2,
                           y2 + z2 - r2 - x2,
                           z2 - y2 + x2 - r2);
    }
    __syncthreads();
    const float4 u = u_sh;

    const size_t base = (size_t)bc * SP + (size_t)half * HSP;
    const float4* xp = reinterpret_cast<const float4*>(x) + base;
    float4* op = reinterpret_cast<float4*>(out) + base;
    float4 v[8];
    #pragma unroll
    for (int j = 0; j < 8; j++) v[j] = __ldcs(&xp[t + j * TPB]);
    #pragma unroll
    for (int j = 0; j < 8; j++) {
        __stcs(&op[t + j * TPB],
               make_float4(v[j].x * u.x, v[j].y * u.y,
                           v[j].z * u.z, v[j].w * u.w));
    }
}

// ---------------------------------------------------------------------------
// Generic launch: np pool units (full slabs from pool_b0) and ns scale units
// (half slabs from scale_b0), Bresenham-interleaved over np+ns blocks.
// ---------------------------------------------------------------------------
__global__ void __launch_bounds__(TPB) step_kernel(const float* __restrict__ x,
                                                   const float* __restrict__ comp_w,
                                                   const float* __restrict__ comp_b,
                                                   const float* __restrict__ exc_w,
                                                   const float* __restrict__ exc_b,
                                                   float* __restrict__ out,
                                                   int scale_b0, int ns,
                                                   int pool_b0, int np) {
    const long r = blockIdx.x;
    const long tot = np + ns;
    const int p_lo = (int)((r * np) / tot);
    const int p_hi = (int)(((r + 1) * np) / tot);
    if (p_hi > p_lo) {
        do_pool(x, pool_b0 * NC + p_lo);
    } else {
        const int sidx = (int)r - p_hi;
        do_scale_half(x, comp_w, comp_b, exc_w, exc_b, out,
                      scale_b0 * NC + (sidx >> 1), sidx & 1);
    }
}

extern "C" void kernel_launch(void* const* d_in, const int* in_sizes, int n_in,
                              void* d_out, int out_size) {
    const float* x      = (const float*)d_in[0];
    const float* comp_w = (const float*)d_in[1];
    const float* comp_b = (const float*)d_in[2];
    const float* exc_w  = (const float*)d_in[3];
    const float* exc_b  = (const float*)d_in[4];
    float* out = (float*)d_out;

    // Tapered chunk table: batch start and count. 1,2,2,2,2,2,2,2,1.
    const int cb[9] = {0, 1, 3, 5, 7, 9, 11, 13, 15};
    const int cn[9] = {1, 2, 2, 2, 2, 2, 2, 2, 1};

    // L0: pool chunk 0 (16 MB)
    step_kernel<<<cn[0] * NC, TPB>>>(x, comp_w, comp_b, exc_w, exc_b, out,
                                     0, 0, cb[0], cn[0] * NC);
    // L1..L8: combined scale(c_{k-1}) + pool(c_k)
    for (int k = 1; k <= 8; k++) {
        int ns = cn[k - 1] * NC * 2;
        int np = cn[k] * NC;
        step_kernel<<<np + ns, TPB>>>(x, comp_w, comp_b, exc_w, exc_b, out,
                                      cb[k - 1], ns, cb[k], np);
    }
    // L9: scale chunk 8 (16 MB)
    step_kernel<<<cn[8] * NC * 2, TPB>>>(x, comp_w, comp_b, exc_w, exc_b, out,
                                         cb[8], cn[8] * NC * 2, 0, 0);
}

// round 15
// speedup vs baseline: 1.2523x; 1.1510x over previous
#include <cuda_runtime.h>
#include <cuda_bf16.h>
#include <math.h>
#include <stdint.h>

// x: (16, 256, 64, 64, 4) f32. Per (b,c) slab = 4096 float4 = 64 KB.
// R11 structure (best: 111.1us) + PDL overlap:
//   chunk = 2 batches = 32 MB; serial chain on one stream:
//     L0: pool(c0); Lk: combined scale(c_{k-1})+pool(c_k) k=1..7; L8: scale(c7)
//   Every launch: programmatic stream serialization. Every block triggers
//   launch-completion at entry. Only SCALE blocks grid-dependency-sync
//   (they need g_pooled from the previous launch); POOL blocks start
//   immediately and fill the previous launch's drain bubble with DRAM reads.
// Pool unit = full slab (64 KB read). Scale unit = half slab
// (32 KB __ldcs L2 read + 32 KB __stcs streamed write).

#define NB 16
#define NC 256
#define SP 4096                      // float4 per (b,c)
#define HSP (SP / 2)
#define CHUNK_B 2
#define NCHUNKS (NB / CHUNK_B)       // 8
#define CHUNK_SLABS (CHUNK_B * NC)   // 512
#define TPB 256
#define GRP 8

__device__ float4 g_pooled[NB * NC];

// ---------------------------------------------------------------------------
__device__ __forceinline__ void do_pool(const float* __restrict__ x, int bc) {
    const float4* xp = reinterpret_cast<const float4*>(x) + (size_t)bc * SP;
    const int t = threadIdx.x;

    float4 m = make_float4(-INFINITY, -INFINITY, -INFINITY, -INFINITY);
    #pragma unroll
    for (int j0 = 0; j0 < SP / TPB; j0 += GRP) {
        float4 v[GRP];
        #pragma unroll
        for (int j = 0; j < GRP; j++) v[j] = xp[t + (j0 + j) * TPB];
        #pragma unroll
        for (int j = 0; j < GRP; j++) {
            m.x = fmaxf(m.x, v[j].x);
            m.y = fmaxf(m.y, v[j].y);
            m.z = fmaxf(m.z, v[j].z);
            m.w = fmaxf(m.w, v[j].w);
        }
    }
    #pragma unroll
    for (int o = 16; o > 0; o >>= 1) {
        m.x = fmaxf(m.x, __shfl_xor_sync(0xffffffffu, m.x, o));
        m.y = fmaxf(m.y, __shfl_xor_sync(0xffffffffu, m.y, o));
        m.z = fmaxf(m.z, __shfl_xor_sync(0xffffffffu, m.z, o));
        m.w = fmaxf(m.w, __shfl_xor_sync(0xffffffffu, m.w, o));
    }
    __shared__ float4 red[TPB / 32];
    if ((t & 31) == 0) red[t >> 5] = m;
    __syncthreads();
    if (t == 0) {
        float4 r = red[0];
        #pragma unroll
        for (int w = 1; w < TPB / 32; w++) {
            r.x = fmaxf(r.x, red[w].x);
            r.y = fmaxf(r.y, red[w].y);
            r.z = fmaxf(r.z, red[w].z);
            r.w = fmaxf(r.w, red[w].w);
        }
        g_pooled[bc] = r;
    }
}

// ---------------------------------------------------------------------------
__device__ __forceinline__ void do_scale_half(const float* __restrict__ x,
                                              const float* __restrict__ comp_w,
                                              const float* __restrict__ comp_b,
                                              const float* __restrict__ exc_w,
                                              const float* __restrict__ exc_b,
                                              float* __restrict__ out,
                                              int bc, int half) {
    const int b = bc >> 8;
    const int c = bc & 255;
    const int t = threadIdx.x;
    const int lane = t & 31;
    const int warp = t >> 5;

    __shared__ float4 red[TPB / 32];
    __shared__ float4 u_sh;

    float4 p = g_pooled[b * NC + t];
    float s0 = p.x * comp_w[0 * NC + t];
    float s1 = p.y * comp_w[1 * NC + t];
    float s2 = p.z * comp_w[2 * NC + t];
    float s3 = p.w * comp_w[3 * NC + t];
    #pragma unroll
    for (int o = 16; o > 0; o >>= 1) {
        s0 += __shfl_xor_sync(0xffffffffu, s0, o);
        s1 += __shfl_xor_sync(0xffffffffu, s1, o);
        s2 += __shfl_xor_sync(0xffffffffu, s2, o);
        s3 += __shfl_xor_sync(0xffffffffu, s3, o);
    }
    if (lane == 0) red[warp] = make_float4(s0, s1, s2, s3);
    __syncthreads();
    if (t == 0) {
        float r  = comp_b[0];
        float xc = comp_b[1];
        float yc = comp_b[2];
        float zc = comp_b[3];
        #pragma unroll
        for (int w = 0; w < TPB / 32; w++) {
            r  += red[w].x;
            xc += red[w].y;
            yc += red[w].z;
            zc += red[w].w;
        }
        float u1r = r + xc + yc + zc;
        float u1x = xc - r - zc + yc;
        float u1y = yc + zc - r - xc;
        float u1z = zc - yc + xc - r;
        float r2 = u1r * exc_w[0 * NC + c] + exc_b[0 * NC + c];
        float x2 = u1x * exc_w[1 * NC + c] + exc_b[1 * NC + c];
        float y2 = u1y * exc_w[2 * NC + c] + exc_b[2 * NC + c];
        float z2 = u1z * exc_w[3 * NC + c] + exc_b[3 * NC + c];
        u_sh = make_float4(r2 + x2 + y2 + z2,
                           x2 - r2 - z2 + y2,
                           y2 + z2 - r2 - x2,
                           z2 - y2 + x2 - r2);
    }
    __syncthreads();
    const float4 u = u_sh;

    const size_t base = (size_t)bc * SP + (size_t)half * HSP;
    const float4* xp = reinterpret_cast<const float4*>(x) + base;
    float4* op = reinterpret_cast<float4*>(out) + base;
    float4 v[GRP];
    #pragma unroll
    for (int j = 0; j < GRP; j++) v[j] = __ldcs(&xp[t + j * TPB]);
    #pragma unroll
    for (int j = 0; j < GRP; j++) {
        __stcs(&op[t + j * TPB],
               make_float4(v[j].x * u.x, v[j].y * u.y,
                           v[j].z * u.z, v[j].w * u.w));
    }
}

// ---------------------------------------------------------------------------
__global__ void __launch_bounds__(TPB) pool_only_kernel(const float* __restrict__ x,
                                                        int b0) {
    cudaTriggerProgrammaticLaunchCompletion();
    do_pool(x, b0 * NC + blockIdx.x);
}

__global__ void __launch_bounds__(TPB) scale_only_kernel(const float* __restrict__ x,
                                                         const float* __restrict__ comp_w,
                                                         const float* __restrict__ comp_b,
                                                         const float* __restrict__ exc_w,
                                                         const float* __restrict__ exc_b,
                                                         float* __restrict__ out,
                                                         int b0) {
    cudaTriggerProgrammaticLaunchCompletion();
    cudaGridDependencySynchronize();   // need previous launch's g_pooled
    do_scale_half(x, comp_w, comp_b, exc_w, exc_b, out,
                  b0 * NC + (int)(blockIdx.x >> 1), blockIdx.x & 1);
}

__global__ void __launch_bounds__(TPB) combined_kernel(const float* __restrict__ x,
                                                       const float* __restrict__ comp_w,
                                                       const float* __restrict__ comp_b,
                                                       const float* __restrict__ exc_w,
                                                       const float* __restrict__ exc_b,
                                                       float* __restrict__ out,
                                                       int scale_b0, int pool_b0) {
    cudaTriggerProgrammaticLaunchCompletion();
    const int sid  = blockIdx.x / 3;
    const int role = blockIdx.x % 3;
    if (role == 0) {
        // Pool blocks: no dependency on the previous launch -> start now.
        do_pool(x, pool_b0 * NC + sid);
    } else {
        // Scale blocks: need g_pooled written by the previous launch.
        cudaGridDependencySynchronize();
        do_scale_half(x, comp_w, comp_b, exc_w, exc_b, out,
                      scale_b0 * NC + sid, role - 1);
    }
}

// ---------------------------------------------------------------------------
template <typename... Args>
static inline void launch_pdl(void (*kern)(Args...), int grid, Args... args) {
    cudaLaunchConfig_t cfg = {};
    cfg.gridDim = dim3(grid);
    cfg.blockDim = dim3(TPB);
    cfg.dynamicSmemBytes = 0;
    cfg.stream = 0;
    cudaLaunchAttribute attr[1];
    attr[0].id = cudaLaunchAttributeProgrammaticStreamSerialization;
    attr[0].val.programmaticStreamSerializationAllowed = 1;
    cfg.attrs = attr;
    cfg.numAttrs = 1;
    cudaLaunchKernelEx(&cfg, kern, args...);
}

extern "C" void kernel_launch(void* const* d_in, const int* in_sizes, int n_in,
                              void* d_out, int out_size) {
    const float* x      = (const float*)d_in[0];
    const float* comp_w = (const float*)d_in[1];
    const float* comp_b = (const float*)d_in[2];
    const float* exc_w  = (const float*)d_in[3];
    const float* exc_b  = (const float*)d_in[4];
    float* out = (float*)d_out;

    launch_pdl(pool_only_kernel, CHUNK_SLABS, x, 0);
    for (int q = 0; q + 1 < NCHUNKS; q++) {
        launch_pdl(combined_kernel, 3 * CHUNK_SLABS,
                   x, comp_w, comp_b, exc_w, exc_b, out,
                   q * CHUNK_B, (q + 1) * CHUNK_B);
    }
    launch_pdl(scale_only_kernel, 2 * CHUNK_SLABS,
               x, comp_w, comp_b, exc_w, exc_b, out,
               (NCHUNKS - 1) * CHUNK_B);
}